// round 8
// baseline (speedup 1.0000x reference)
#include <cuda_runtime.h>
#include <math.h>

// ---------------------------------------------------------------------------
// HMM forward (CgpHmmCell, nCodons=2): 24 states, CTX=6.
// 8 batch rows per warp = TWO independent 4-row chains (A, B) interleaved per
// time step for in-warp ILP; 8 lanes per row, 3 states per lane; 4 width-8
// shfls per chain-step. E loads prefetched 2 steps ahead per chain.
// Deferred exact power-of-two renormalization every 16 steps.
// ---------------------------------------------------------------------------

#define NSTATES 24

__device__ float g_Wl[8][12];        // per-sublane edge weights (11 used)
__device__ float g_Bt4[216 * 32];    // emission float4: [ctx][sub][4] (k=3 pad)
__device__ float g_pi[32];           // softmax(init)

__constant__ int c_rcnt[24] = {2,1,1,4,1,1,3,1,1,2,1,1,1,2,1,1,2,1,1,2,1,1,2,1};
__constant__ int c_rcols[24][4] = {
  {0,1,0,0},{2,0,0,0},{3,0,0,0},{4,14,7,10},{5,0,0,0},{6,0,0,0},{7,17,10,0},
  {8,0,0,0},{9,0,0,0},{20,10,0,0},{11,0,0,0},{12,0,0,0},{13,0,0,0},{13,23,0,0},
  {15,0,0,0},{16,0,0,0},{4,14,0,0},{18,0,0,0},{19,0,0,0},{7,17,0,0},{21,0,0,0},
  {22,0,0,0},{10,20,0,0},{23,0,0,0}};

__constant__ int c_sr0[8] = {0,0,1,1,1,2,3,0};  // shfl of a0 (first)
__constant__ int c_sr1[8] = {0,0,0,2,0,0,0,0};  // shfl of a0 (second)
__constant__ int c_sr2[8] = {0,5,6,7,5,6,7,4};  // shfl of a1
__constant__ int c_sr3[8] = {0,0,1,2,3,4,5,6};  // shfl of a2

// ---------------------------------------------------------------------------
__global__ void setup_kernel(const float* __restrict__ w,
                             const float* __restrict__ ew,
                             const float* __restrict__ ik) {
  __shared__ float V[24][24];
  __shared__ float A[24][24];
  int tid = threadIdx.x;
  for (int i = tid; i < 576; i += blockDim.x) {
    ((float*)V)[i] = 0.f;
    ((float*)A)[i] = 0.f;
  }
  __syncthreads();
  if (tid == 0) {
    float w12 = w[12];
    V[0][0]  = 1.f - w[0]; V[0][1]  = w[0];
    V[1][2]  = 1.f;        V[2][3]  = 1.f;
    V[3][4]  = w[1];       V[6][7]  = w[2];
    V[4][5]  = 1.f; V[7][8] = 1.f; V[5][6] = 1.f; V[8][9] = 1.f;
    V[3][14] = w[3]; V[6][17] = w[4]; V[9][20] = w[5];
    V[9][10] = 1.f - w[5];
    V[14][15] = 1.f; V[17][18] = 1.f; V[20][21] = 1.f;
    V[15][16] = 1.f; V[18][19] = 1.f; V[21][22] = 1.f;
    V[16][4] = w[6]; V[19][7] = w[7]; V[22][10] = w[8];
    V[16][14] = 1.f - w[9]; V[19][17] = 1.f - w[10]; V[22][20] = 1.f - w[11];
    V[3][7]  = 1.f - w12 * w12;
    V[3][10] = 1.f - w12 * w12 * w12;
    V[6][10] = 1.f - w12 * w12;
    V[10][11] = 1.f; V[11][12] = 1.f; V[12][13] = 1.f;
    V[13][13] = 1.f; V[13][23] = 1.f; V[23][23] = 1.f;
  }
  __syncthreads();
  if (tid < 24) {
    int n = c_rcnt[tid];
    float m = -1e30f;
    for (int i = 0; i < n; ++i) m = fmaxf(m, V[tid][c_rcols[tid][i]]);
    float Z = 0.f;
    for (int i = 0; i < n; ++i) Z += expf(V[tid][c_rcols[tid][i]] - m);
    for (int i = 0; i < n; ++i) {
      int c = c_rcols[tid][i];
      A[tid][c] = expf(V[tid][c] - m) / Z;
    }
  }
  __syncthreads();
  // slots: 0:w0a(r0) 1:w0b(r3) | 2:wa(a0) 3:wb(a1) 4:wc(r0) 5:wd(r1) 6:we(r2)
  //        7:wf(a1) 8:wg(r0) 9:wh(r2) 10:wi(a2)
  if (tid == 0) {
    for (int s = 0; s < 8; ++s)
      for (int k = 0; k < 12; ++k) g_Wl[s][k] = 0.f;
    g_Wl[0][0]=A[0][0];  g_Wl[0][2]=A[0][1];   g_Wl[0][7]=A[1][2];
    g_Wl[1][1]=A[2][3];  g_Wl[1][2]=A[3][4];   g_Wl[1][6]=A[16][4];  g_Wl[1][7]=A[4][5];
    g_Wl[2][1]=A[5][6];  g_Wl[2][4]=A[3][7];   g_Wl[2][2]=A[6][7];   g_Wl[2][6]=A[19][7];  g_Wl[2][7]=A[7][8];
    g_Wl[3][1]=A[8][9];  g_Wl[3][4]=A[3][10];  g_Wl[3][5]=A[6][10];  g_Wl[3][2]=A[9][10];  g_Wl[3][6]=A[22][10]; g_Wl[3][7]=A[10][11];
    g_Wl[4][1]=A[11][12];g_Wl[4][2]=A[12][13]; g_Wl[4][3]=A[13][13]; g_Wl[4][8]=A[3][14];  g_Wl[4][9]=A[16][14];
    g_Wl[5][1]=A[14][15];g_Wl[5][2]=A[15][16]; g_Wl[5][8]=A[6][17];  g_Wl[5][9]=A[19][17];
    g_Wl[6][1]=A[17][18];g_Wl[6][2]=A[18][19]; g_Wl[6][8]=A[9][20];  g_Wl[6][9]=A[22][20];
    g_Wl[7][1]=A[20][21];g_Wl[7][2]=A[21][22]; g_Wl[7][9]=A[13][23]; g_Wl[7][10]=A[23][23];
  }
  if (tid == 32) {
    float m = -1e30f;
    for (int s = 0; s < NSTATES; ++s) m = fmaxf(m, ik[s]);
    float Z = 0.f;
    for (int s = 0; s < NSTATES; ++s) Z += expf(ik[s] - m);
    for (int s = 0; s < 32; ++s)
      g_pi[s] = (s < NSTATES) ? expf(ik[s] - m) / Z : 0.f;
  }
  for (int idx = tid; idx < 216 * 32; idx += blockDim.x) {
    int r = idx & 31, ctx = idx >> 5;
    int sub = r >> 2, k = r & 3;
    int pp = ctx / 36, rm = ctx - pp * 36;
    int p = rm / 6, c = rm - p * 6;
    float val = 0.f;
    if (k < 3) {
      int st = 3 * sub + k;
      val = 1.f / 6.f;
      if (st < 17 && pp < 4 && p < 4 && c < 4) {
        const float* e = ew + (((st * 4) + pp) * 4 + p) * 4;
        float m = fmaxf(fmaxf(e[0], e[1]), fmaxf(e[2], e[3]));
        float Z = expf(e[0] - m) + expf(e[1] - m) + expf(e[2] - m) + expf(e[3] - m);
        val = expf(e[c] - m) / Z;
      }
    }
    g_Bt4[idx] = val;
  }
}

// ---------------------------------------------------------------------------
// pack 16 ctx indices (8 bits each) into 4 uints; advances (pr, m1) carry
#define PACKW(dst, pr, m1, sx, sy, sz, sw)                             \
  {                                                                    \
    int _c0 = pr * 6 + (sx); pr = m1 * 6 + (sx); m1 = (sx);            \
    int _c1 = pr * 6 + (sy); pr = m1 * 6 + (sy); m1 = (sy);            \
    int _c2 = pr * 6 + (sz); pr = m1 * 6 + (sz); m1 = (sz);            \
    int _c3 = pr * 6 + (sw); pr = m1 * 6 + (sw); m1 = (sw);            \
    dst = (unsigned)_c0 | ((unsigned)_c1 << 8) | ((unsigned)_c2 << 16) \
        | ((unsigned)_c3 << 24);                                       \
  }

// load 2 emission float4s from bytes [sh, sh+8) of packed word pk
#define LOAD2(d0, d1, pk, sh)                            \
  {                                                      \
    unsigned _w = (pk) >> (sh);                          \
    d0 = Bt[(int)(_w & 255u) * 8 + sub];                 \
    d1 = Bt[(int)((_w >> 8) & 255u) * 8 + sub];          \
  }

// one recurrence step on alpha set (A0,A1,A2); pred then post-multiply by E
#define STEP(A0, A1, A2, Ev)                                                \
  {                                                                         \
    float _r0 = __shfl_sync(F, A0, sr0, 8);                                 \
    float _r1 = __shfl_sync(F, A0, sr1, 8);                                 \
    float _r2 = __shfl_sync(F, A1, sr2, 8);                                 \
    float _r3 = __shfl_sync(F, A2, sr3, 8);                                 \
    float _p1l = fmaf(wa, A0, wb * A1);                                     \
    float _p2l = fmaf(wf, A1, wi * A2);                                     \
    float _p0 = fmaf(w0a, _r0, w0b * _r3);                                  \
    float _p1 = _p1l + fmaf(wc, _r0, fmaf(wd, _r1, we * _r2));              \
    float _p2 = _p2l + fmaf(wg, _r0, wh * _r2);                             \
    A0 = _p0 * (Ev).x; A1 = _p1 * (Ev).y; A2 = _p2 * (Ev).z;                \
  }

// renorm one chain: exact power-of-two rescale, lagged bookkeeping
#define RENORM(A0, A1, A2, PEND, EK, KK, ZL)                 \
  {                                                          \
    A0 *= PEND; A1 *= PEND; A2 *= PEND;                      \
    KK += (float)EK;                                         \
    float _z = A0 + A1 + A2;                                 \
    _z += __shfl_xor_sync(F, _z, 4, 8);                      \
    _z += __shfl_xor_sync(F, _z, 2, 8);                      \
    _z += __shfl_xor_sync(F, _z, 1, 8);                      \
    int _ez = ((__float_as_int(_z) >> 23) & 0xff) - 127;     \
    PEND = __int_as_float((127 - _ez) << 23);                \
    EK = _ez;                                                \
    ZL = _z;                                                 \
  }

__global__ void __launch_bounds__(32)
fwd_kernel(const int* __restrict__ seq, float* __restrict__ out, int T) {
  const unsigned F = 0xffffffffu;
  int lane = threadIdx.x & 31;
  int sub = lane & 7;
  int g = lane >> 3;
  int rowA = blockIdx.x * 8 + g;
  int rowB = rowA + 4;
  const int4* spA = (const int4*)(seq + (long long)rowA * T);
  const int4* spB = (const int4*)(seq + (long long)rowB * T);

  float w0a = g_Wl[sub][0], w0b = g_Wl[sub][1];
  float wa  = g_Wl[sub][2], wb  = g_Wl[sub][3], wc = g_Wl[sub][4];
  float wd  = g_Wl[sub][5], we  = g_Wl[sub][6];
  float wf  = g_Wl[sub][7], wg  = g_Wl[sub][8], wh = g_Wl[sub][9];
  float wi  = g_Wl[sub][10];
  int sr0 = c_sr0[sub], sr1 = c_sr1[sub], sr2 = c_sr2[sub], sr3 = c_sr3[sub];

  float a0 = g_pi[3 * sub + 0], a1 = g_pi[3 * sub + 1], a2 = g_pi[3 * sub + 2];
  float b0 = a0, b1 = a1, b2 = a2;

  const float4* Bt = (const float4*)g_Bt4;  // index: ctx*8 + sub

  int prA = 28, m1A = 4, prB = 28, m1B = 4;   // start-context (4,4)
  float KA = 0.f, pendA = 1.f, zlA = 1.f;  int eKA = 0;
  float KB = 0.f, pendB = 1.f, zlB = 1.f;  int eKB = 0;
  int nblk = T >> 4;           // T = 2000 = 125*16

  // --- prologue: block 0 packed ctx; prefetch steps 0-1 of both chains -----
  unsigned cwA0, cwA1, cwA2, cwA3, cwB0, cwB1, cwB2, cwB3;
  {
    int4 t0 = spA[0], t1 = spA[1], t2 = spA[2], t3 = spA[3];
    PACKW(cwA0, prA, m1A, t0.x, t0.y, t0.z, t0.w);
    PACKW(cwA1, prA, m1A, t1.x, t1.y, t1.z, t1.w);
    PACKW(cwA2, prA, m1A, t2.x, t2.y, t2.z, t2.w);
    PACKW(cwA3, prA, m1A, t3.x, t3.y, t3.z, t3.w);
    int4 u0 = spB[0], u1 = spB[1], u2 = spB[2], u3 = spB[3];
    PACKW(cwB0, prB, m1B, u0.x, u0.y, u0.z, u0.w);
    PACKW(cwB1, prB, m1B, u1.x, u1.y, u1.z, u1.w);
    PACKW(cwB2, prB, m1B, u2.x, u2.y, u2.z, u2.w);
    PACKW(cwB3, prB, m1B, u3.x, u3.y, u3.z, u3.w);
  }
  float4 XA0, XA1, YA0, YA1;   // chain A: current / next 2-step E buffers
  float4 XB0, XB1, YB0, YB1;   // chain B
  LOAD2(XA0, XA1, cwA0, 0);
  LOAD2(XB0, XB1, cwB0, 0);

  for (int i = 0; i < nblk; ++i) {
    // prefetch next block's symbols -> packed ctx (last iter: dummy, unused)
    unsigned nwA0, nwA1, nwA2, nwA3, nwB0, nwB1, nwB2, nwB3;
    {
      int nb = (i + 1 < nblk) ? (i + 1) : 0;
      int4 t0 = spA[nb*4+0], t1 = spA[nb*4+1], t2 = spA[nb*4+2], t3 = spA[nb*4+3];
      PACKW(nwA0, prA, m1A, t0.x, t0.y, t0.z, t0.w);
      PACKW(nwA1, prA, m1A, t1.x, t1.y, t1.z, t1.w);
      PACKW(nwA2, prA, m1A, t2.x, t2.y, t2.z, t2.w);
      PACKW(nwA3, prA, m1A, t3.x, t3.y, t3.z, t3.w);
      int4 u0 = spB[nb*4+0], u1 = spB[nb*4+1], u2 = spB[nb*4+2], u3 = spB[nb*4+3];
      PACKW(nwB0, prB, m1B, u0.x, u0.y, u0.z, u0.w);
      PACKW(nwB1, prB, m1B, u1.x, u1.y, u1.z, u1.w);
      PACKW(nwB2, prB, m1B, u2.x, u2.y, u2.z, u2.w);
      PACKW(nwB3, prB, m1B, u3.x, u3.y, u3.z, u3.w);
    }

    // chunk 0: steps 0-1; prefetch 2-3
    LOAD2(YA0, YA1, cwA0, 16); LOAD2(YB0, YB1, cwB0, 16);
    if (i == 0) {                       // t=0: pred = pi (no transition)
      a0 *= XA0.x; a1 *= XA0.y; a2 *= XA0.z;
      b0 *= XB0.x; b1 *= XB0.y; b2 *= XB0.z;
    } else {
      STEP(a0, a1, a2, XA0); STEP(b0, b1, b2, XB0);
    }
    STEP(a0, a1, a2, XA1); STEP(b0, b1, b2, XB1);
    // chunk 1: steps 2-3; prefetch 4-5
    LOAD2(XA0, XA1, cwA1, 0); LOAD2(XB0, XB1, cwB1, 0);
    STEP(a0, a1, a2, YA0); STEP(b0, b1, b2, YB0);
    STEP(a0, a1, a2, YA1); STEP(b0, b1, b2, YB1);
    // chunk 2: steps 4-5; prefetch 6-7
    LOAD2(YA0, YA1, cwA1, 16); LOAD2(YB0, YB1, cwB1, 16);
    STEP(a0, a1, a2, XA0); STEP(b0, b1, b2, XB0);
    STEP(a0, a1, a2, XA1); STEP(b0, b1, b2, XB1);
    // chunk 3: steps 6-7; prefetch 8-9
    LOAD2(XA0, XA1, cwA2, 0); LOAD2(XB0, XB1, cwB2, 0);
    STEP(a0, a1, a2, YA0); STEP(b0, b1, b2, YB0);
    STEP(a0, a1, a2, YA1); STEP(b0, b1, b2, YB1);
    // chunk 4: steps 8-9; prefetch 10-11
    LOAD2(YA0, YA1, cwA2, 16); LOAD2(YB0, YB1, cwB2, 16);
    STEP(a0, a1, a2, XA0); STEP(b0, b1, b2, XB0);
    STEP(a0, a1, a2, XA1); STEP(b0, b1, b2, XB1);
    // chunk 5: steps 10-11; prefetch 12-13
    LOAD2(XA0, XA1, cwA3, 0); LOAD2(XB0, XB1, cwB3, 0);
    STEP(a0, a1, a2, YA0); STEP(b0, b1, b2, YB0);
    STEP(a0, a1, a2, YA1); STEP(b0, b1, b2, YB1);
    // chunk 6: steps 12-13; prefetch 14-15
    LOAD2(YA0, YA1, cwA3, 16); LOAD2(YB0, YB1, cwB3, 16);
    STEP(a0, a1, a2, XA0); STEP(b0, b1, b2, XB0);
    STEP(a0, a1, a2, XA1); STEP(b0, b1, b2, XB1);
    // chunk 7: steps 14-15; prefetch next block steps 0-1
    LOAD2(XA0, XA1, nwA0, 0); LOAD2(XB0, XB1, nwB0, 0);
    STEP(a0, a1, a2, YA0); STEP(b0, b1, b2, YB0);
    STEP(a0, a1, a2, YA1); STEP(b0, b1, b2, YB1);

    // --- lagged exact power-of-two renorm (both chains) --------------------
    RENORM(a0, a1, a2, pendA, eKA, KA, zlA);
    RENORM(b0, b1, b2, pendB, eKB, KB, zlB);

    cwA0 = nwA0; cwA1 = nwA1; cwA2 = nwA2; cwA3 = nwA3;
    cwB0 = nwB0; cwB1 = nwB1; cwB2 = nwB2; cwB3 = nwB3;
  }

  if (sub == 0) {
    out[rowA] = (__log2f(zlA) + KA) * 0.69314718055994530942f;
    out[rowB] = (__log2f(zlB) + KB) * 0.69314718055994530942f;
  }
}

// ---------------------------------------------------------------------------
extern "C" void kernel_launch(void* const* d_in, const int* in_sizes, int n_in,
                              void* d_out, int out_size) {
  const float* w  = (const float*)d_in[0];   // transition_kernel (240)
  const float* ew = (const float*)d_in[1];   // emission_kernel (1088)
  const float* ik = (const float*)d_in[2];   // init_kernel (24)
  const int* seq  = (const int*)d_in[3];     // (batch, T)
  float* out = (float*)d_out;

  int batch = out_size;                      // 2048
  int T = in_sizes[3] / batch;               // 2000

  setup_kernel<<<1, 256>>>(w, ew, ik);
  fwd_kernel<<<batch / 8, 32>>>(seq, out, T);
}

// round 9
// speedup vs baseline: 1.4711x; 1.4711x over previous
#include <cuda_runtime.h>
#include <math.h>

// ---------------------------------------------------------------------------
// HMM forward (CgpHmmCell, nCodons=2): 24 states, CTX=6.
// 4 batch rows per warp, 8 lanes per row, 3 states per lane.
// Cross-lane alpha exchange via STS/LDS (in-order per-warp shared pipe) —
// 3 stores + 4 pipelined loads per step instead of 4 serialized shfls.
// E loads double-buffered 2 steps ahead; symbols + packed ctx prefetched one
// 16-step block ahead. Deferred exact power-of-two renorm every 16 steps.
// ---------------------------------------------------------------------------

#define NSTATES 24

__device__ float g_Wl[8][12];        // per-sublane edge weights (11 used)
__device__ float g_Bt4[216 * 32];    // emission float4: [ctx][sub][4] (k=3 pad)
__device__ float g_pi[32];           // softmax(init)

__constant__ int c_rcnt[24] = {2,1,1,4,1,1,3,1,1,2,1,1,1,2,1,1,2,1,1,2,1,1,2,1};
__constant__ int c_rcols[24][4] = {
  {0,1,0,0},{2,0,0,0},{3,0,0,0},{4,14,7,10},{5,0,0,0},{6,0,0,0},{7,17,10,0},
  {8,0,0,0},{9,0,0,0},{20,10,0,0},{11,0,0,0},{12,0,0,0},{13,0,0,0},{13,23,0,0},
  {15,0,0,0},{16,0,0,0},{4,14,0,0},{18,0,0,0},{19,0,0,0},{7,17,0,0},{21,0,0,0},
  {22,0,0,0},{10,20,0,0},{23,0,0,0}};

// source sublanes for the 4 cross-lane fetches (indices within 8-lane group)
__constant__ int c_sr0[8] = {0,0,1,1,1,2,3,0};  // read of slot a0 (first)
__constant__ int c_sr1[8] = {0,0,0,2,0,0,0,0};  // read of slot a0 (second)
__constant__ int c_sr2[8] = {0,5,6,7,5,6,7,4};  // read of slot a1
__constant__ int c_sr3[8] = {0,0,1,2,3,4,5,6};  // read of slot a2

// ---------------------------------------------------------------------------
__global__ void setup_kernel(const float* __restrict__ w,
                             const float* __restrict__ ew,
                             const float* __restrict__ ik) {
  __shared__ float V[24][24];
  __shared__ float A[24][24];
  int tid = threadIdx.x;
  for (int i = tid; i < 576; i += blockDim.x) {
    ((float*)V)[i] = 0.f;
    ((float*)A)[i] = 0.f;
  }
  __syncthreads();
  if (tid == 0) {
    float w12 = w[12];
    V[0][0]  = 1.f - w[0]; V[0][1]  = w[0];
    V[1][2]  = 1.f;        V[2][3]  = 1.f;
    V[3][4]  = w[1];       V[6][7]  = w[2];
    V[4][5]  = 1.f; V[7][8] = 1.f; V[5][6] = 1.f; V[8][9] = 1.f;
    V[3][14] = w[3]; V[6][17] = w[4]; V[9][20] = w[5];
    V[9][10] = 1.f - w[5];
    V[14][15] = 1.f; V[17][18] = 1.f; V[20][21] = 1.f;
    V[15][16] = 1.f; V[18][19] = 1.f; V[21][22] = 1.f;
    V[16][4] = w[6]; V[19][7] = w[7]; V[22][10] = w[8];
    V[16][14] = 1.f - w[9]; V[19][17] = 1.f - w[10]; V[22][20] = 1.f - w[11];
    V[3][7]  = 1.f - w12 * w12;
    V[3][10] = 1.f - w12 * w12 * w12;
    V[6][10] = 1.f - w12 * w12;
    V[10][11] = 1.f; V[11][12] = 1.f; V[12][13] = 1.f;
    V[13][13] = 1.f; V[13][23] = 1.f; V[23][23] = 1.f;
  }
  __syncthreads();
  if (tid < 24) {
    int n = c_rcnt[tid];
    float m = -1e30f;
    for (int i = 0; i < n; ++i) m = fmaxf(m, V[tid][c_rcols[tid][i]]);
    float Z = 0.f;
    for (int i = 0; i < n; ++i) Z += expf(V[tid][c_rcols[tid][i]] - m);
    for (int i = 0; i < n; ++i) {
      int c = c_rcols[tid][i];
      A[tid][c] = expf(V[tid][c] - m) / Z;
    }
  }
  __syncthreads();
  // slots: 0:w0a(r0) 1:w0b(r3) | 2:wa(a0) 3:wb(a1) 4:wc(r0) 5:wd(r1) 6:we(r2)
  //        7:wf(a1) 8:wg(r0) 9:wh(r2) 10:wi(a2)
  if (tid == 0) {
    for (int s = 0; s < 8; ++s)
      for (int k = 0; k < 12; ++k) g_Wl[s][k] = 0.f;
    g_Wl[0][0]=A[0][0];  g_Wl[0][2]=A[0][1];   g_Wl[0][7]=A[1][2];
    g_Wl[1][1]=A[2][3];  g_Wl[1][2]=A[3][4];   g_Wl[1][6]=A[16][4];  g_Wl[1][7]=A[4][5];
    g_Wl[2][1]=A[5][6];  g_Wl[2][4]=A[3][7];   g_Wl[2][2]=A[6][7];   g_Wl[2][6]=A[19][7];  g_Wl[2][7]=A[7][8];
    g_Wl[3][1]=A[8][9];  g_Wl[3][4]=A[3][10];  g_Wl[3][5]=A[6][10];  g_Wl[3][2]=A[9][10];  g_Wl[3][6]=A[22][10]; g_Wl[3][7]=A[10][11];
    g_Wl[4][1]=A[11][12];g_Wl[4][2]=A[12][13]; g_Wl[4][3]=A[13][13]; g_Wl[4][8]=A[3][14];  g_Wl[4][9]=A[16][14];
    g_Wl[5][1]=A[14][15];g_Wl[5][2]=A[15][16]; g_Wl[5][8]=A[6][17];  g_Wl[5][9]=A[19][17];
    g_Wl[6][1]=A[17][18];g_Wl[6][2]=A[18][19]; g_Wl[6][8]=A[9][20];  g_Wl[6][9]=A[22][20];
    g_Wl[7][1]=A[20][21];g_Wl[7][2]=A[21][22]; g_Wl[7][9]=A[13][23]; g_Wl[7][10]=A[23][23];
  }
  if (tid == 32) {
    float m = -1e30f;
    for (int s = 0; s < NSTATES; ++s) m = fmaxf(m, ik[s]);
    float Z = 0.f;
    for (int s = 0; s < NSTATES; ++s) Z += expf(ik[s] - m);
    for (int s = 0; s < 32; ++s)
      g_pi[s] = (s < NSTATES) ? expf(ik[s] - m) / Z : 0.f;
  }
  for (int idx = tid; idx < 216 * 32; idx += blockDim.x) {
    int r = idx & 31, ctx = idx >> 5;
    int sub = r >> 2, k = r & 3;
    int pp = ctx / 36, rm = ctx - pp * 36;
    int p = rm / 6, c = rm - p * 6;
    float val = 0.f;
    if (k < 3) {
      int st = 3 * sub + k;
      val = 1.f / 6.f;
      if (st < 17 && pp < 4 && p < 4 && c < 4) {
        const float* e = ew + (((st * 4) + pp) * 4 + p) * 4;
        float m = fmaxf(fmaxf(e[0], e[1]), fmaxf(e[2], e[3]));
        float Z = expf(e[0] - m) + expf(e[1] - m) + expf(e[2] - m) + expf(e[3] - m);
        val = expf(e[c] - m) / Z;
      }
    }
    g_Bt4[idx] = val;
  }
}

// ---------------------------------------------------------------------------
// pack 16 ctx indices (8 bits each) into 4 uints; advances (pair, m1) carry
#define PACKW(dst, sx, sy, sz, sw)                                     \
  {                                                                    \
    int _c0 = pair * 6 + (sx); pair = m1 * 6 + (sx); m1 = (sx);        \
    int _c1 = pair * 6 + (sy); pair = m1 * 6 + (sy); m1 = (sy);        \
    int _c2 = pair * 6 + (sz); pair = m1 * 6 + (sz); m1 = (sz);        \
    int _c3 = pair * 6 + (sw); pair = m1 * 6 + (sw); m1 = (sw);        \
    dst = (unsigned)_c0 | ((unsigned)_c1 << 8) | ((unsigned)_c2 << 16) \
        | ((unsigned)_c3 << 24);                                       \
  }

// load 2 emission float4s from bytes [sh, sh+8) of packed word pk
#define LOAD2(d0, d1, pk, sh)                            \
  {                                                      \
    unsigned _w = (pk) >> (sh);                          \
    d0 = Bt[(int)(_w & 255u) * 8 + sub];                 \
    d1 = Bt[(int)((_w >> 8) & 255u) * 8 + sub];          \
  }

// one recurrence step: publish alphas to smem, read 4 remotes (pipelined LDS),
// combine, post-multiply by E.  asm volatile preserves STS->LDS order; the
// per-warp shared pipe executes them in order, so no sync is needed (single
// warp per block, no divergence).
#define STEP(A0, A1, A2, Ev)                                                \
  {                                                                         \
    asm volatile("st.shared.f32 [%0], %1;" :: "r"(sb), "f"(A0));            \
    asm volatile("st.shared.f32 [%0+32], %1;" :: "r"(sb), "f"(A1));         \
    asm volatile("st.shared.f32 [%0+64], %1;" :: "r"(sb), "f"(A2));         \
    float _r0, _r1, _r2, _r3;                                               \
    asm volatile("ld.shared.f32 %0, [%1];" : "=f"(_r0) : "r"(ra0));         \
    asm volatile("ld.shared.f32 %0, [%1];" : "=f"(_r1) : "r"(ra1));         \
    asm volatile("ld.shared.f32 %0, [%1];" : "=f"(_r2) : "r"(ra2));         \
    asm volatile("ld.shared.f32 %0, [%1];" : "=f"(_r3) : "r"(ra3));         \
    float _p1l = fmaf(wa, A0, wb * A1);                                     \
    float _p2l = fmaf(wf, A1, wi * A2);                                     \
    float _p0 = fmaf(w0a, _r0, w0b * _r3);                                  \
    float _p1 = _p1l + fmaf(wc, _r0, fmaf(wd, _r1, we * _r2));              \
    float _p2 = _p2l + fmaf(wg, _r0, wh * _r2);                             \
    A0 = _p0 * (Ev).x; A1 = _p1 * (Ev).y; A2 = _p2 * (Ev).z;                \
  }

__global__ void __launch_bounds__(32)
fwd_kernel(const int* __restrict__ seq, float* __restrict__ out, int T) {
  const unsigned F = 0xffffffffu;
  // exchange buffer: 4 groups x 40 floats (slots: a0 @ +sub, a1 @ +8+sub,
  // a2 @ +16+sub; stride 40 floats => store banks (8g+sub)%32 all distinct,
  // each load's banks distinct across groups, duplicates = broadcast)
  __shared__ float xch[4 * 40];
  int lane = threadIdx.x & 31;
  int sub = lane & 7;
  int g = lane >> 3;
  int row = blockIdx.x * 4 + g;
  const int4* sp = (const int4*)(seq + (long long)row * T);

  unsigned gb;
  {
    unsigned base;
    asm("{ .reg .u64 t; cvta.to.shared.u64 t, %1; cvt.u32.u64 %0, t; }"
        : "=r"(base) : "l"(xch));
    gb = base + (unsigned)(g * 160);
  }
  unsigned sb  = gb + (unsigned)(sub * 4);
  unsigned ra0 = gb + (unsigned)(c_sr0[sub] * 4);
  unsigned ra1 = gb + (unsigned)(c_sr1[sub] * 4);
  unsigned ra2 = gb + 32u + (unsigned)(c_sr2[sub] * 4);
  unsigned ra3 = gb + 64u + (unsigned)(c_sr3[sub] * 4);

  float w0a = g_Wl[sub][0], w0b = g_Wl[sub][1];
  float wa  = g_Wl[sub][2], wb  = g_Wl[sub][3], wc = g_Wl[sub][4];
  float wd  = g_Wl[sub][5], we  = g_Wl[sub][6];
  float wf  = g_Wl[sub][7], wg  = g_Wl[sub][8], wh = g_Wl[sub][9];
  float wi  = g_Wl[sub][10];

  float a0 = g_pi[3 * sub + 0];
  float a1 = g_pi[3 * sub + 1];
  float a2 = g_pi[3 * sub + 2];

  const float4* Bt = (const float4*)g_Bt4;  // index: ctx*8 + sub

  int pair = 28, m1 = 4;       // start-context (prev2=4, prev1=4)
  float K = 0.f, pend = 1.f, zlast = 1.f;
  int eK = 0;
  int nblk = T >> 4;           // T = 2000 = 125*16

  // --- prologue: block 0 packed ctx; prefetch steps 0-1 --------------------
  unsigned cw0, cw1, cw2, cw3;
  {
    int4 t0 = sp[0], t1 = sp[1], t2 = sp[2], t3 = sp[3];
    PACKW(cw0, t0.x, t0.y, t0.z, t0.w);
    PACKW(cw1, t1.x, t1.y, t1.z, t1.w);
    PACKW(cw2, t2.x, t2.y, t2.z, t2.w);
    PACKW(cw3, t3.x, t3.y, t3.z, t3.w);
  }
  float4 X0, X1, Y0, Y1;       // double-buffered 2-step E chunks
  LOAD2(X0, X1, cw0, 0);

  for (int i = 0; i < nblk; ++i) {
    // prefetch next block's symbols -> packed ctx (last iter: dummy, unused)
    unsigned nw0, nw1, nw2, nw3;
    {
      int nb = (i + 1 < nblk) ? (i + 1) : 0;
      int4 t0 = sp[nb*4+0], t1 = sp[nb*4+1], t2 = sp[nb*4+2], t3 = sp[nb*4+3];
      PACKW(nw0, t0.x, t0.y, t0.z, t0.w);
      PACKW(nw1, t1.x, t1.y, t1.z, t1.w);
      PACKW(nw2, t2.x, t2.y, t2.z, t2.w);
      PACKW(nw3, t3.x, t3.y, t3.z, t3.w);
    }

    // steps 0-1; prefetch 2-3
    LOAD2(Y0, Y1, cw0, 16);
    if (i == 0) {                       // t=0: pred = pi (no transition)
      a0 *= X0.x; a1 *= X0.y; a2 *= X0.z;
    } else {
      STEP(a0, a1, a2, X0);
    }
    STEP(a0, a1, a2, X1);
    // steps 2-3; prefetch 4-5
    LOAD2(X0, X1, cw1, 0);
    STEP(a0, a1, a2, Y0); STEP(a0, a1, a2, Y1);
    // steps 4-5; prefetch 6-7
    LOAD2(Y0, Y1, cw1, 16);
    STEP(a0, a1, a2, X0); STEP(a0, a1, a2, X1);
    // steps 6-7; prefetch 8-9
    LOAD2(X0, X1, cw2, 0);
    STEP(a0, a1, a2, Y0); STEP(a0, a1, a2, Y1);
    // steps 8-9; prefetch 10-11
    LOAD2(Y0, Y1, cw2, 16);
    STEP(a0, a1, a2, X0); STEP(a0, a1, a2, X1);
    // steps 10-11; prefetch 12-13
    LOAD2(X0, X1, cw3, 0);
    STEP(a0, a1, a2, Y0); STEP(a0, a1, a2, Y1);
    // steps 12-13; prefetch 14-15
    LOAD2(Y0, Y1, cw3, 16);
    STEP(a0, a1, a2, X0); STEP(a0, a1, a2, X1);
    // steps 14-15; prefetch next block steps 0-1
    LOAD2(X0, X1, nw0, 0);
    STEP(a0, a1, a2, Y0); STEP(a0, a1, a2, Y1);

    // --- lagged exact power-of-two renorm --------------------------------
    // (shfl latency here overlaps following steps: consumers are a block away)
    a0 *= pend; a1 *= pend; a2 *= pend;
    K += (float)eK;
    float z = a0 + a1 + a2;
    z += __shfl_xor_sync(F, z, 4, 8);
    z += __shfl_xor_sync(F, z, 2, 8);
    z += __shfl_xor_sync(F, z, 1, 8);
    int ez = ((__float_as_int(z) >> 23) & 0xff) - 127;
    pend = __int_as_float((127 - ez) << 23);  // 2^{-ez}, exact
    eK = ez;
    zlast = z;

    cw0 = nw0; cw1 = nw1; cw2 = nw2; cw3 = nw3;
  }

  if (sub == 0) out[row] = (__log2f(zlast) + K) * 0.69314718055994530942f;
}

// ---------------------------------------------------------------------------
extern "C" void kernel_launch(void* const* d_in, const int* in_sizes, int n_in,
                              void* d_out, int out_size) {
  const float* w  = (const float*)d_in[0];   // transition_kernel (240)
  const float* ew = (const float*)d_in[1];   // emission_kernel (1088)
  const float* ik = (const float*)d_in[2];   // init_kernel (24)
  const int* seq  = (const int*)d_in[3];     // (batch, T)
  float* out = (float*)d_out;

  int batch = out_size;                      // 2048
  int T = in_sizes[3] / batch;               // 2000

  setup_kernel<<<1, 256>>>(w, ew, ik);
  fwd_kernel<<<batch / 4, 32>>>(seq, out, T);
}